// round 6
// baseline (speedup 1.0000x reference)
#include <cuda_runtime.h>
#include <cstdint>
#include <math.h>

#define N_NODES 65536
#define C       256
#define B       8
#define EMB     512
#define NET     7
#define NNT     7
#define E_EDGES (N_NODES * 7)
#define EPS     1e-5f
#define NBLK    512            /* row blocks of 128 */
#define CAP     2048           /* max edges per 128-row block (mean 896) */

// ---------------- scratch (device globals; no allocs allowed) ----------------
__device__ float    g_h[(size_t)N_NODES * C];     // GN output (h1, then h3)
__device__ float    g_h2[(size_t)N_NODES * C];    // conv1 raw output
__device__ float    g_S[B * C];
__device__ float    g_S2[B * C];
__device__ int      g_cnt[B];
__device__ float    g_mean[B * C];
__device__ float    g_istd[B * C];
__device__ float    g_emb[B * C];
__device__ int      g_bcnt[NBLK];
__device__ unsigned g_bins[(size_t)NBLK * CAP];

// ---------------- helpers ----------------
__device__ __forceinline__ float to_tf32(float x) {
    float r;
    asm("cvt.rna.tf32.f32 %0, %1;" : "=f"(r) : "f"(x));
    return r;
}
__device__ __forceinline__ float silu(float z) {
    return z / (1.0f + __expf(-z));
}
__device__ __forceinline__ void mma8(float* d, const float* a, const float* b) {
    asm volatile(
        "mma.sync.aligned.m16n8k8.row.col.f32.tf32.tf32.f32 "
        "{%0,%1,%2,%3}, {%4,%5,%6,%7}, {%8,%9}, {%0,%1,%2,%3};"
        : "+f"(d[0]), "+f"(d[1]), "+f"(d[2]), "+f"(d[3])
        : "r"(__float_as_uint(a[0])), "r"(__float_as_uint(a[1])),
          "r"(__float_as_uint(a[2])), "r"(__float_as_uint(a[3])),
          "r"(__float_as_uint(b[0])), "r"(__float_as_uint(b[1])));
}

// ---------------- zero per-call state (one kernel) ----------------
__global__ void zero_all(float* S, float* S2, int* cnt, int* bcnt) {
    int i = blockIdx.x * 256 + threadIdx.x;
    if (i < B * C) { S[i] = 0.0f; S2[i] = 0.0f; }
    if (i < B) cnt[i] = 0;
    if (i < NBLK) bcnt[i] = 0;
}

// ---------------- edge binning: one kernel replaces the CSR build ----------------
// entry pack: t[3] @26 | nt[3] @23 | r[7] @16 | col[16] @0
__global__ void bin_fill(const int* __restrict__ ei, const int* __restrict__ et,
                         const int* __restrict__ ntype,
                         int* bcnt, unsigned* bins) {
    int e = blockIdx.x * 256 + threadIdx.x;
    if (e >= E_EDGES) return;
    int row = ei[e];
    int col = ei[E_EDGES + e];
    int t   = et[e];
    int nt  = ntype[col];
    int blk = row >> 7;
    int r   = row & 127;
    int pos = atomicAdd(&bcnt[blk], 1);
    if (pos < CAP)
        bins[(size_t)blk * CAP + pos] =
            ((unsigned)t << 26) | ((unsigned)nt << 23) | ((unsigned)r << 16) | (unsigned)col;
}

// ---------------- group norm ----------------
// 512 blocks x 256 threads; block covers 128 contiguous (sorted-batch) nodes.
__global__ void gn_stats(const float* __restrict__ x, const int* __restrict__ bid,
                         const float* __restrict__ addB,
                         float* S, float* S2, int* cnt) {
    const int c  = threadIdx.x;
    const int n0 = blockIdx.x * 128;
    float s = 0.0f, s2 = 0.0f;
    int curb = bid[n0];
    int lc = 0;
    for (int n = n0; n < n0 + 128; n++) {
        int b = bid[n];
        if (b != curb) {
            atomicAdd(&S[curb * C + c], s);
            atomicAdd(&S2[curb * C + c], s2);
            if (c == 0) atomicAdd(&cnt[curb], lc);
            s = 0.0f; s2 = 0.0f; lc = 0; curb = b;
        }
        float v = x[(size_t)n * C + c];
        if (addB) v += addB[b * C + c];
        s += v; s2 += v * v; lc++;
    }
    atomicAdd(&S[curb * C + c], s);
    atomicAdd(&S2[curb * C + c], s2);
    if (c == 0) atomicAdd(&cnt[curb], lc);
}

// grid = B, block = 256. cpg = 8. Also resets S/S2/cnt for the next GN round.
__global__ void gn_finalize(float* S, float* S2, int* cnt,
                            float* meanA, float* istdA) {
    __shared__ float sS[C], sS2[C];
    const int c = threadIdx.x;
    const int b = blockIdx.x;
    sS[c]  = S[b * C + c];
    sS2[c] = S2[b * C + c];
    __syncthreads();
    const int g0 = (c >> 3) << 3;
    float Sg = 0.0f, S2g = 0.0f;
#pragma unroll
    for (int j = 0; j < 8; j++) { Sg += sS[g0 + j]; S2g += sS2[g0 + j]; }
    float count = (float)cnt[b] * 8.0f;
    float ic  = 1.0f / (count + EPS);
    float mu  = Sg * ic;
    float var = (S2g - 2.0f * mu * Sg + count * mu * mu) * ic;
    float istd = 1.0f / sqrtf(var + EPS);
    meanA[b * C + c] = mu;
    istdA[b * C + c] = istd;
    // reset for next GN round
    S[b * C + c]  = 0.0f;
    S2[b * C + c] = 0.0f;
    if (c == 0) cnt[b] = 0;
}

// grid = N, block = 256: out = silu(((x+add) - mean)*istd*w + b)
__global__ void gn_norm_silu(const float* __restrict__ x, const int* __restrict__ bid,
                             const float* __restrict__ addB,
                             const float* __restrict__ meanA, const float* __restrict__ istdA,
                             const float* __restrict__ w, const float* __restrict__ bb,
                             float* __restrict__ out) {
    const int i = blockIdx.x;
    const int c = threadIdx.x;
    const int b = bid[i];
    float v = x[(size_t)i * C + c];
    if (addB) v += addB[b * C + c];
    float z = (v - meanA[b * C + c]) * istdA[b * C + c] * w[c] + bb[c];
    out[(size_t)i * C + c] = silu(z);
}

// ---------------- emb projection: silu(emb) @ emb_w + emb_b ----------------
__global__ void emb_proj(const float* __restrict__ emb, const float* __restrict__ ew,
                         const float* __restrict__ eb, float* __restrict__ out) {
    __shared__ float se[EMB];
    const int b = blockIdx.x;
    const int o = threadIdx.x;
    for (int k = o; k < EMB; k += 256) se[k] = silu(emb[b * EMB + k]);
    __syncthreads();
    float acc = eb[o];
#pragma unroll 8
    for (int k = 0; k < EMB; k++) acc += se[k] * ew[k * C + o];
    out[b * C + o] = acc;
}

// ---------------- fused graph conv ----------------
// out[i, o] = base + sum_t sum_k G[i,t,k] * cw[(t*263+k)*256+o],
//   G[i,t,k<256]   = sum_{e in (i,t)} h[col_e, k]
//   G[i,t,256+j]   = #{e in (i,t): nt[col_e]==j}     (9th chunk per type)
// Tile: 128 rows x 128 out-cols, K chunks of 32, 63 chunks total.
#define AS_ST 36
#define BS_ST 136

__global__ void __launch_bounds__(256, 2)
conv_fused(const float* __restrict__ h, const float* __restrict__ cw,
           const int* __restrict__ bcnt, const unsigned* __restrict__ bins,
           const int* __restrict__ bid,
           const float* __restrict__ addB, const float* __restrict__ addN,
           float* __restrict__ out) {
    __shared__ float As[128 * AS_ST];          // 18.4 KB (aggregated A tile)
    __shared__ float Bs[32 * BS_ST];           // 17.4 KB (tf32 W tile)
    __shared__ unsigned sorted[CAP];           // 8 KB (edges sorted by (t, r&7))
    __shared__ int scnt[56], soff[57], sfill[56];

    const int tid  = threadIdx.x;
    const int lane = tid & 31;
    const int warp = tid >> 5;
    const int wm = warp & 3, wn = warp >> 2;
    const int gID = lane >> 2, tig = lane & 3;

    const int blk   = blockIdx.y;
    const int row0  = blk * 128;
    const int oBase = blockIdx.x * 128;

    // ---- staging: counting sort of this block's edges by key (t*8 + (r&7)) ----
    unsigned* raw = (unsigned*)As;   // alias; staging finishes before chunk loop
    int count = bcnt[blk];
    if (count > CAP) count = CAP;
    if (tid < 56) scnt[tid] = 0;
    __syncthreads();
    for (int i = tid; i < count; i += 256) {
        unsigned u = bins[(size_t)blk * CAP + i];
        raw[i] = u;
        int key = ((u >> 26) & 7) * 8 + ((u >> 16) & 7);
        atomicAdd(&scnt[key], 1);
    }
    __syncthreads();
    if (tid == 0) {
        int run = 0;
        for (int k = 0; k < 56; k++) { soff[k] = run; sfill[k] = run; run += scnt[k]; }
        soff[56] = run;
    }
    __syncthreads();
    for (int i = tid; i < count; i += 256) {
        unsigned u = raw[i];
        int key = ((u >> 26) & 7) * 8 + ((u >> 16) & 7);
        int p = atomicAdd(&sfill[key], 1);
        sorted[p] = u;
    }
    __syncthreads();

    float acc[2][8][4];
#pragma unroll
    for (int a = 0; a < 2; a++)
#pragma unroll
        for (int b2 = 0; b2 < 8; b2++)
#pragma unroll
            for (int c2 = 0; c2 < 4; c2++) acc[a][b2][c2] = 0.0f;

    const int bk = tid >> 3;             // Bs row this thread loads
    const int bc0 = (tid & 7) * 16;      // Bs col base (16 floats)

    for (int ch = 0; ch < 63; ch++) {
        const int t   = ch / 9;
        const int sub = ch - t * 9;

        // zero A tile (cols 0..31)
        for (int ii = tid; ii < 4096; ii += 256)
            As[(ii >> 5) * AS_ST + (ii & 31)] = 0.0f;
        __syncthreads();

        // aggregate: warp w owns rows with (r & 7) == w  -> race-free plain RMW
        {
            const int key = t * 8 + warp;
            int i = soff[key], iend = soff[key + 1];
            if (sub < 8) {
                const int kh0 = sub * 32;
                for (; i + 1 < iend; i += 2) {
                    unsigned u0 = sorted[i], u1 = sorted[i + 1];
                    float v0 = h[(size_t)(u0 & 0xFFFF) * C + kh0 + lane];
                    float v1 = h[(size_t)(u1 & 0xFFFF) * C + kh0 + lane];
                    int r0 = (u0 >> 16) & 127, r1 = (u1 >> 16) & 127;
                    As[r0 * AS_ST + lane] += v0;
                    As[r1 * AS_ST + lane] += v1;
                }
                if (i < iend) {
                    unsigned u = sorted[i];
                    As[((u >> 16) & 127) * AS_ST + lane] +=
                        h[(size_t)(u & 0xFFFF) * C + (sub * 32) + lane];
                }
            } else {
                // one-hot count chunk
                if (lane == 0)
                    for (; i < iend; i++) {
                        unsigned u = sorted[i];
                        As[((u >> 16) & 127) * AS_ST + ((u >> 23) & 7)] += 1.0f;
                    }
            }
        }

        // load W tile (tf32), rows k of chunk; one-hot chunk uses rows 256..262
        {
            bool valid = (sub < 8) || (bk < NNT);
            size_t wrow = (sub < 8) ? (size_t)(t * 263 + sub * 32 + bk)
                                    : (size_t)(t * 263 + 256 + bk);
#pragma unroll
            for (int q = 0; q < 4; q++) {
                float4 v = valid ? *(const float4*)&cw[wrow * C + oBase + bc0 + q * 4]
                                 : make_float4(0.f, 0.f, 0.f, 0.f);
                v.x = to_tf32(v.x); v.y = to_tf32(v.y);
                v.z = to_tf32(v.z); v.w = to_tf32(v.w);
                *(float4*)&Bs[bk * BS_ST + bc0 + q * 4] = v;
            }
        }
        __syncthreads();

        // mma over the 32-wide chunk
#pragma unroll
        for (int k8 = 0; k8 < 32; k8 += 8) {
            float afrag[2][4];
#pragma unroll
            for (int mf = 0; mf < 2; mf++) {
                int r = wm * 32 + mf * 16 + gID;
                afrag[mf][0] = to_tf32(As[r * AS_ST + k8 + tig]);
                afrag[mf][1] = to_tf32(As[(r + 8) * AS_ST + k8 + tig]);
                afrag[mf][2] = to_tf32(As[r * AS_ST + k8 + tig + 4]);
                afrag[mf][3] = to_tf32(As[(r + 8) * AS_ST + k8 + tig + 4]);
            }
            float bfrag[8][2];
#pragma unroll
            for (int nf = 0; nf < 8; nf++) {
                int cc = wn * 64 + nf * 8 + gID;
                bfrag[nf][0] = Bs[(k8 + tig) * BS_ST + cc];
                bfrag[nf][1] = Bs[(k8 + tig + 4) * BS_ST + cc];
            }
#pragma unroll
            for (int mf = 0; mf < 2; mf++)
#pragma unroll
                for (int nf = 0; nf < 8; nf++)
                    mma8(acc[mf][nf], afrag[mf], bfrag[nf]);
        }
        __syncthreads();
    }

    // ---- epilogue: add base (per-batch or per-node or none), store ----
#pragma unroll
    for (int mf = 0; mf < 2; mf++) {
        int rLo = row0 + wm * 32 + mf * 16 + gID;
        int rHi = rLo + 8;
        int bLo = 0, bHi = 0;
        if (addB) { bLo = bid[rLo]; bHi = bid[rHi]; }
#pragma unroll
        for (int nf = 0; nf < 8; nf++) {
            int colG = oBase + wn * 64 + nf * 8 + tig * 2;
            float a0 = acc[mf][nf][0], a1 = acc[mf][nf][1];
            float a2 = acc[mf][nf][2], a3 = acc[mf][nf][3];
            if (addB) {
                a0 += addB[bLo * C + colG];     a1 += addB[bLo * C + colG + 1];
                a2 += addB[bHi * C + colG];     a3 += addB[bHi * C + colG + 1];
            } else if (addN) {
                a0 += addN[(size_t)rLo * C + colG];     a1 += addN[(size_t)rLo * C + colG + 1];
                a2 += addN[(size_t)rHi * C + colG];     a3 += addN[(size_t)rHi * C + colG + 1];
            }
            *(float2*)&out[(size_t)rLo * C + colG] = make_float2(a0, a1);
            *(float2*)&out[(size_t)rHi * C + colG] = make_float2(a2, a3);
        }
    }
}

// ---------------- host ----------------
extern "C" void kernel_launch(void* const* d_in, const int* in_sizes, int n_in,
                              void* d_out, int out_size) {
    const float* x       = (const float*)d_in[0];
    const float* emb     = (const float*)d_in[1];
    const int*   bid     = (const int*)d_in[2];
    const int*   ei      = (const int*)d_in[3];
    const int*   et      = (const int*)d_in[4];
    const int*   ntype   = (const int*)d_in[5];
    const float* gn1_w   = (const float*)d_in[6];
    const float* gn1_b   = (const float*)d_in[7];
    const float* conv1_w = (const float*)d_in[8];
    const float* emb_w   = (const float*)d_in[9];
    const float* emb_b   = (const float*)d_in[10];
    const float* gn2_w   = (const float*)d_in[11];
    const float* gn2_b   = (const float*)d_in[12];
    const float* conv2_w = (const float*)d_in[13];
    float* out = (float*)d_out;

    float *S, *S2, *meanA, *istdA, *h, *h2, *embO;
    int *cnt, *bcnt;
    unsigned* bins;
    cudaGetSymbolAddress((void**)&S,     g_S);
    cudaGetSymbolAddress((void**)&S2,    g_S2);
    cudaGetSymbolAddress((void**)&cnt,   g_cnt);
    cudaGetSymbolAddress((void**)&meanA, g_mean);
    cudaGetSymbolAddress((void**)&istdA, g_istd);
    cudaGetSymbolAddress((void**)&h,     g_h);
    cudaGetSymbolAddress((void**)&h2,    g_h2);
    cudaGetSymbolAddress((void**)&embO,  g_emb);
    cudaGetSymbolAddress((void**)&bcnt,  g_bcnt);
    cudaGetSymbolAddress((void**)&bins,  g_bins);

    dim3 convGrid(2, NBLK);  // (out-col tile, row block)

    // launch order chosen so index 5 (ncu -s 5 -c 1) == conv_fused (conv1)
    zero_all<<<8, 256>>>(S, S2, cnt, bcnt);                                   // 0
    bin_fill<<<E_EDGES / 256, 256>>>(ei, et, ntype, bcnt, bins);              // 1
    gn_stats<<<NBLK, 256>>>(x, bid, nullptr, S, S2, cnt);                     // 2
    gn_finalize<<<B, 256>>>(S, S2, cnt, meanA, istdA);                        // 3
    gn_norm_silu<<<N_NODES, 256>>>(x, bid, nullptr, meanA, istdA,
                                   gn1_w, gn1_b, h);                          // 4
    conv_fused<<<convGrid, 256>>>(h, conv1_w, bcnt, bins, bid,
                                  nullptr, nullptr, h2);                      // 5 <- ncu
    emb_proj<<<B, 256>>>(emb, emb_w, emb_b, embO);                            // 6
    gn_stats<<<NBLK, 256>>>(h2, bid, embO, S, S2, cnt);                       // 7
    gn_finalize<<<B, 256>>>(S, S2, cnt, meanA, istdA);                        // 8
    gn_norm_silu<<<N_NODES, 256>>>(h2, bid, embO, meanA, istdA,
                                   gn2_w, gn2_b, h);                          // 9
    conv_fused<<<convGrid, 256>>>(h, conv2_w, bcnt, bins, bid,
                                  nullptr, x, out);                           // 10

    (void)in_sizes; (void)n_in; (void)out_size;
}

// round 11
// speedup vs baseline: 1.8653x; 1.8653x over previous
#include <cuda_runtime.h>
#include <cuda_fp16.h>
#include <cstdint>
#include <math.h>

#define N_NODES 65536
#define C       256
#define B       8
#define EMB     512
#define NET     7
#define NNT     7
#define E_EDGES (N_NODES * 7)
#define NCOLS   (NET * C)      /* 1792 */
#define EPS     1e-5f

// ---------------- scratch (device globals; zero-initialized at load) ----------------
__device__ __half   g_hh[(size_t)N_NODES * C];       // GN output (fp16), GEMM A
__device__ float    g_h2[(size_t)N_NODES * C];       // conv1 out + emb (fp32)
__device__ __half   g_Y[(size_t)N_NODES * NCOLS];    // GEMM out (235 MB, fp16)
__device__ __half   g_Wh[2][(size_t)NCOLS * C];      // transposed fp16 weights [n][k]
__device__ float    g_TB[2][NET * NNT * C];          // one-hot bias tables
__device__ float    g_S[B * C];
__device__ float    g_S2[B * C];
__device__ int      g_cnt[B];
__device__ int      g_done;
__device__ float    g_mean[B * C];
__device__ float    g_istd[B * C];
__device__ float    g_emb[B * C];
__device__ int      g_deg[N_NODES];
__device__ int      g_fill[N_NODES];
__device__ int      g_rp[N_NODES];
__device__ int      g_bsum[256];
__device__ unsigned g_ct[E_EDGES];

// ---------------- helpers ----------------
__device__ __forceinline__ float silu(float z) {
    return z / (1.0f + __expf(-z));
}
__device__ __forceinline__ void mma16(float* d, const unsigned* a, const unsigned* b) {
    asm volatile(
        "mma.sync.aligned.m16n8k16.row.col.f32.f16.f16.f32 "
        "{%0,%1,%2,%3}, {%4,%5,%6,%7}, {%8,%9}, {%0,%1,%2,%3};"
        : "+f"(d[0]), "+f"(d[1]), "+f"(d[2]), "+f"(d[3])
        : "r"(a[0]), "r"(a[1]), "r"(a[2]), "r"(a[3]),
          "r"(b[0]), "r"(b[1]));
}

// ---------------- zero deg/fill (only state not self-resetting) ----------------
__global__ void zero_df(int* deg, int* fill) {
    int i = blockIdx.x * 256 + threadIdx.x;
    deg[i] = 0;
    fill[i] = 0;
}

// ---------------- weight restructure (transpose + tb in one kernel) ----------------
// Wh[n][k] = half(cw[(t*263+k)*256+o]),  n = t*256+o, k<256
// TB[(t*7+nt)*256+o] = cw[(t*263+256+nt)*256+o]
__global__ void build_w(const float* __restrict__ cw, __half* __restrict__ Wh,
                        float* __restrict__ TB) {
    __shared__ float tile[32][33];
    const int tx = threadIdx.x;   // 32
    const int ty = threadIdx.y;   // 8
    const int by = blockIdx.y;    // 56 n-tiles
    const int t  = by >> 3;
    const int o0 = (by & 7) * 32;
    if (blockIdx.x < 8) {
        const int k0 = blockIdx.x * 32;
        for (int ki = ty; ki < 32; ki += 8)
            tile[ki][tx] = cw[(size_t)(t * 263 + k0 + ki) * C + o0 + tx];
        __syncthreads();
        for (int r = ty; r < 32; r += 8)
            Wh[(size_t)(t * 256 + o0 + r) * C + k0 + tx] = __float2half_rn(tile[tx][r]);
    } else {
        // TB portion: ty = nt (0..6)
        if (ty < NNT)
            TB[(size_t)(t * NNT + ty) * C + o0 + tx] =
                cw[(size_t)(t * 263 + 256 + ty) * C + o0 + tx];
    }
}

// ---------------- group norm: stats + fused last-block finalize ----------------
// 512 blocks x 256 threads; block covers 128 contiguous (sorted-batch) nodes.
__global__ void gn_stats_f(const float* __restrict__ x, const int* __restrict__ bid,
                           float* S, float* S2, int* cnt,
                           float* meanA, float* istdA) {
    const int c  = threadIdx.x;
    const int n0 = blockIdx.x * 128;
    float s = 0.0f, s2 = 0.0f;
    int curb = bid[n0];
    int lc = 0;
    for (int n = n0; n < n0 + 128; n++) {
        int b = bid[n];
        if (b != curb) {
            atomicAdd(&S[curb * C + c], s);
            atomicAdd(&S2[curb * C + c], s2);
            if (c == 0) atomicAdd(&cnt[curb], lc);
            s = 0.0f; s2 = 0.0f; lc = 0; curb = b;
        }
        float v = x[(size_t)n * C + c];
        s += v; s2 += v * v; lc++;
    }
    atomicAdd(&S[curb * C + c], s);
    atomicAdd(&S2[curb * C + c], s2);
    if (c == 0) atomicAdd(&cnt[curb], lc);

    // last block finalizes
    __threadfence();
    __shared__ int isLast;
    __shared__ float sS[C], sS2[C];
    if (c == 0) isLast = (atomicAdd(&g_done, 1) == gridDim.x - 1);
    __syncthreads();
    if (!isLast) return;
    for (int b = 0; b < B; b++) {
        int cb = cnt[b];
        sS[c]  = S[b * C + c];
        sS2[c] = S2[b * C + c];
        __syncthreads();
        const int g0 = (c >> 3) << 3;
        float Sg = 0.0f, S2g = 0.0f;
#pragma unroll
        for (int j = 0; j < 8; j++) { Sg += sS[g0 + j]; S2g += sS2[g0 + j]; }
        float count = (float)cb * 8.0f;
        float ic  = 1.0f / (count + EPS);
        float mu  = Sg * ic;
        float var = (S2g - 2.0f * mu * Sg + count * mu * mu) * ic;
        meanA[b * C + c] = mu;
        istdA[b * C + c] = 1.0f / sqrtf(var + EPS);
        S[b * C + c]  = 0.0f;
        S2[b * C + c] = 0.0f;
        if (c == 0) cnt[b] = 0;
        __syncthreads();
    }
    if (c == 0) g_done = 0;
}

// grid = N, block = 256: out_half = silu((x - mean)*istd*w + b)
__global__ void gn_norm_silu(const float* __restrict__ x, const int* __restrict__ bid,
                             const float* __restrict__ meanA, const float* __restrict__ istdA,
                             const float* __restrict__ w, const float* __restrict__ bb,
                             __half* __restrict__ out) {
    const int i = blockIdx.x;
    const int c = threadIdx.x;
    const int b = bid[i];
    float v = x[(size_t)i * C + c];
    float z = (v - meanA[b * C + c]) * istdA[b * C + c] * w[c] + bb[c];
    out[(size_t)i * C + c] = __float2half_rn(silu(z));
}

// ---------------- CSR build ----------------
__global__ void csr_deg(const int* __restrict__ ei, int* deg) {
    int e = blockIdx.x * 256 + threadIdx.x;
    if (e < E_EDGES) atomicAdd(&deg[ei[e]], 1);
}
__global__ void scan1(const int* __restrict__ deg, int* rp, int* bsum) {
    __shared__ int sm[256];
    int t = threadIdx.x;
    int i = blockIdx.x * 256 + t;
    int v = deg[i];
    sm[t] = v;
    __syncthreads();
    for (int off = 1; off < 256; off <<= 1) {
        int add = (t >= off) ? sm[t - off] : 0;
        __syncthreads();
        sm[t] += add;
        __syncthreads();
    }
    rp[i] = sm[t] - v;
    if (t == 255) bsum[blockIdx.x] = sm[255];
}
__global__ void scan2(int* bsum) {
    __shared__ int sm[256];
    int t = threadIdx.x;
    int v = bsum[t];
    sm[t] = v;
    __syncthreads();
    for (int off = 1; off < 256; off <<= 1) {
        int add = (t >= off) ? sm[t - off] : 0;
        __syncthreads();
        sm[t] += add;
        __syncthreads();
    }
    bsum[t] = sm[t] - v;
}
__global__ void scan3(int* rp, const int* __restrict__ bsum) {
    int i = blockIdx.x * 256 + threadIdx.x;
    rp[i] += bsum[blockIdx.x];
}
__global__ void csr_fill(const int* __restrict__ ei, const int* __restrict__ et,
                         const int* __restrict__ rp, int* fill, unsigned* ct) {
    int e = blockIdx.x * 256 + threadIdx.x;
    if (e < E_EDGES) {
        int row = ei[e];
        int col = ei[E_EDGES + e];
        int t   = et[e];
        int pos = rp[row] + atomicAdd(&fill[row], 1);
        ct[pos] = (unsigned)col | ((unsigned)t << 16);
    }
}

// ---------------- emb projection ----------------
__global__ void emb_proj(const float* __restrict__ emb, const float* __restrict__ ew,
                         const float* __restrict__ eb, float* __restrict__ out) {
    __shared__ float se[EMB];
    const int b = blockIdx.x;
    const int o = threadIdx.x;
    for (int k = o; k < EMB; k += 256) se[k] = silu(emb[b * EMB + k]);
    __syncthreads();
    float acc = eb[o];
#pragma unroll 8
    for (int k = 0; k < EMB; k++) acc += se[k] * ew[k * C + o];
    out[b * C + o] = acc;
}

// ---------------- GEMM: Y[N,1792] = hh[N,256] @ Wh^T + TB[nt[row]] (fp16 in, fp32 acc) ----------------
#define AS_ST 56   /* halves; (r*28+tig)%32 hits all banks */
#define BS_ST 56

__global__ void __launch_bounds__(256, 2)
gemm_fp16(const __half* __restrict__ hh, const __half* __restrict__ Wh,
          const float* __restrict__ TB, const int* __restrict__ ntype,
          __half* __restrict__ Y) {
    __shared__ __half As[128 * AS_ST];   // 14.3 KB [row][k]
    __shared__ __half Bs[128 * BS_ST];   // 14.3 KB [n][k]
    __shared__ float  TBs[NNT * 128];    // 3.5 KB

    const int tid  = threadIdx.x;
    const int lane = tid & 31;
    const int warp = tid >> 5;
    const int wm = warp & 3, wn = warp >> 2;
    const int gID = lane >> 2, tig = lane & 3;

    const int rowBase = blockIdx.y * 128;
    const int nBase   = blockIdx.x * 128;
    const int tEdge   = blockIdx.x >> 1;
    const int oInT    = (blockIdx.x & 1) * 128;

    for (int idx = tid; idx < NNT * 128; idx += 256) {
        int nt = idx >> 7;
        int j  = idx & 127;
        TBs[idx] = TB[(size_t)(tEdge * NNT + nt) * C + oInT + j];
    }

    float acc[2][8][4];
#pragma unroll
    for (int a = 0; a < 2; a++)
#pragma unroll
        for (int b2 = 0; b2 < 8; b2++)
#pragma unroll
            for (int c2 = 0; c2 < 4; c2++) acc[a][b2][c2] = 0.0f;

    const int lr  = tid & 127;          // row (A) / n (B) this thread loads
    const int seg = (tid >> 7) * 16;    // 16-half segment

    for (int k0 = 0; k0 < C; k0 += 32) {
        {
            const uint4* sa = (const uint4*)(hh + (size_t)(rowBase + lr) * C + k0 + seg);
            uint4 v0 = sa[0], v1 = sa[1];
            *(uint4*)(As + lr * AS_ST + seg)     = v0;
            *(uint4*)(As + lr * AS_ST + seg + 8) = v1;
            const uint4* sb = (const uint4*)(Wh + (size_t)(nBase + lr) * C + k0 + seg);
            uint4 w0 = sb[0], w1 = sb[1];
            *(uint4*)(Bs + lr * BS_ST + seg)     = w0;
            *(uint4*)(Bs + lr * BS_ST + seg + 8) = w1;
        }
        __syncthreads();

#pragma unroll
        for (int ks = 0; ks < 32; ks += 16) {
            unsigned afrag[2][4];
#pragma unroll
            for (int mf = 0; mf < 2; mf++) {
                int r = wm * 32 + mf * 16 + gID;
                const __half* base = As + r * AS_ST + ks + tig * 2;
                afrag[mf][0] = *(const unsigned*)(base);
                afrag[mf][1] = *(const unsigned*)(base + 8 * AS_ST);
                afrag[mf][2] = *(const unsigned*)(base + 8);
                afrag[mf][3] = *(const unsigned*)(base + 8 * AS_ST + 8);
            }
            unsigned bfrag[8][2];
#pragma unroll
            for (int nf = 0; nf < 8; nf++) {
                int cc = wn * 64 + nf * 8 + gID;
                const __half* base = Bs + cc * BS_ST + ks + tig * 2;
                bfrag[nf][0] = *(const unsigned*)(base);
                bfrag[nf][1] = *(const unsigned*)(base + 8);
            }
#pragma unroll
            for (int mf = 0; mf < 2; mf++)
#pragma unroll
                for (int nf = 0; nf < 8; nf++)
                    mma16(acc[mf][nf], afrag[mf], bfrag[nf]);
        }
        __syncthreads();
    }

    // epilogue: add one-hot bias table, store fp16
#pragma unroll
    for (int mf = 0; mf < 2; mf++) {
        int rLo = rowBase + wm * 32 + mf * 16 + gID;
        int rHi = rLo + 8;
        int ntLo = ntype[rLo];
        int ntHi = ntype[rHi];
#pragma unroll
        for (int nf = 0; nf < 8; nf++) {
            int colL = wn * 64 + nf * 8 + tig * 2;
            int colG = nBase + colL;
            __half2 lo = __floats2half2_rn(acc[mf][nf][0] + TBs[ntLo * 128 + colL],
                                           acc[mf][nf][1] + TBs[ntLo * 128 + colL + 1]);
            __half2 hi = __floats2half2_rn(acc[mf][nf][2] + TBs[ntHi * 128 + colL],
                                           acc[mf][nf][3] + TBs[ntHi * 128 + colL + 1]);
            *(__half2*)&Y[(size_t)rLo * NCOLS + colG] = lo;
            *(__half2*)&Y[(size_t)rHi * NCOLS + colG] = hi;
        }
    }
}

// ---------------- gather: out[i,o] = base + sum_e Y[col_e, t_e*256+o] ----------------
__global__ void gather_add(const __half* __restrict__ Y, const int* __restrict__ rp,
                           const int* __restrict__ deg, const unsigned* __restrict__ ct,
                           const int* __restrict__ bid,
                           const float* __restrict__ addB,
                           const float* __restrict__ addN,
                           float* __restrict__ out) {
    const int i = blockIdx.x;
    const int o = threadIdx.x;
    const int s = rp[i];
    const int d = deg[i];
    float acc;
    if (addB) acc = addB[bid[i] * C + o];
    else      acc = addN[(size_t)i * C + o];
    int e = s;
    for (; e + 1 < s + d; e += 2) {
        unsigned p0 = ct[e], p1 = ct[e + 1];
        float v0 = __half2float(Y[(size_t)(p0 & 0xFFFF) * NCOLS + (p0 >> 16) * C + o]);
        float v1 = __half2float(Y[(size_t)(p1 & 0xFFFF) * NCOLS + (p1 >> 16) * C + o]);
        acc += v0 + v1;
    }
    if (e < s + d) {
        unsigned p = ct[e];
        acc += __half2float(Y[(size_t)(p & 0xFFFF) * NCOLS + (p >> 16) * C + o]);
    }
    out[(size_t)i * C + o] = acc;
}

// ---------------- host ----------------
extern "C" void kernel_launch(void* const* d_in, const int* in_sizes, int n_in,
                              void* d_out, int out_size) {
    const float* x       = (const float*)d_in[0];
    const float* emb     = (const float*)d_in[1];
    const int*   bid     = (const int*)d_in[2];
    const int*   ei      = (const int*)d_in[3];
    const int*   et      = (const int*)d_in[4];
    const int*   ntype   = (const int*)d_in[5];
    const float* gn1_w   = (const float*)d_in[6];
    const float* gn1_b   = (const float*)d_in[7];
    const float* conv1_w = (const float*)d_in[8];
    const float* emb_w   = (const float*)d_in[9];
    const float* emb_b   = (const float*)d_in[10];
    const float* gn2_w   = (const float*)d_in[11];
    const float* gn2_b   = (const float*)d_in[12];
    const float* conv2_w = (const float*)d_in[13];
    float* out = (float*)d_out;

    float *S, *S2, *meanA, *istdA, *h2, *embO, *TBa;
    __half *hh, *Y, *Wha;
    int *cnt, *deg, *fill, *rp, *bsum;
    unsigned* ct;
    cudaGetSymbolAddress((void**)&S,     g_S);
    cudaGetSymbolAddress((void**)&S2,    g_S2);
    cudaGetSymbolAddress((void**)&cnt,   g_cnt);
    cudaGetSymbolAddress((void**)&meanA, g_mean);
    cudaGetSymbolAddress((void**)&istdA, g_istd);
    cudaGetSymbolAddress((void**)&hh,    g_hh);
    cudaGetSymbolAddress((void**)&h2,    g_h2);
    cudaGetSymbolAddress((void**)&Y,     g_Y);
    cudaGetSymbolAddress((void**)&Wha,   g_Wh);
    cudaGetSymbolAddress((void**)&TBa,   g_TB);
    cudaGetSymbolAddress((void**)&embO,  g_emb);
    cudaGetSymbolAddress((void**)&deg,   g_deg);
    cudaGetSymbolAddress((void**)&fill,  g_fill);
    cudaGetSymbolAddress((void**)&rp,    g_rp);
    cudaGetSymbolAddress((void**)&bsum,  g_bsum);
    cudaGetSymbolAddress((void**)&ct,    g_ct);

    __half* Wh1 = Wha;
    __half* Wh2 = Wha + (size_t)NCOLS * C;
    float*  TB1 = TBa;
    float*  TB2 = TBa + NET * NNT * C;

    dim3 wgrid(9, 56), wblk(32, 8);
    dim3 ggrid(NCOLS / 128, N_NODES / 128);  // (14, 512)

    build_w<<<wgrid, wblk>>>(conv1_w, Wh1, TB1);                               // 0
    gn_stats_f<<<512, 256>>>(x, bid, S, S2, cnt, meanA, istdA);                // 1
    gn_norm_silu<<<N_NODES, 256>>>(x, bid, meanA, istdA, gn1_w, gn1_b, hh);    // 2
    gemm_fp16<<<ggrid, 256>>>(hh, Wh1, TB1, ntype, Y);                         // 3 <- ncu?
    zero_df<<<N_NODES / 256, 256>>>(deg, fill);                                // 4
    csr_deg<<<E_EDGES / 256, 256>>>(ei, deg);                                  // 5
    scan1<<<256, 256>>>(deg, rp, bsum);                                        // 6
    scan2<<<1, 256>>>(bsum);                                                   // 7
    scan3<<<256, 256>>>(rp, bsum);                                             // 8
    csr_fill<<<E_EDGES / 256, 256>>>(ei, et, rp, fill, ct);                    // 9
    emb_proj<<<B, 256>>>(emb, emb_w, emb_b, embO);                             // 10
    gather_add<<<N_NODES, 256>>>(Y, rp, deg, ct, bid, embO, nullptr, h2);      // 11
    gn_stats_f<<<512, 256>>>(h2, bid, S, S2, cnt, meanA, istdA);               // 12
    gn_norm_silu<<<N_NODES, 256>>>(h2, bid, meanA, istdA, gn2_w, gn2_b, hh);   // 13
    build_w<<<wgrid, wblk>>>(conv2_w, Wh2, TB2);                               // 14
    gemm_fp16<<<ggrid, 256>>>(hh, Wh2, TB2, ntype, Y);                         // 15
    gather_add<<<N_NODES, 256>>>(Y, rp, deg, ct, bid, nullptr, x, out);        // 16

    (void)in_sizes; (void)n_in; (void)out_size;
}